// round 11
// baseline (speedup 1.0000x reference)
#include <cuda_runtime.h>
#include <cstdint>

// Fixed problem shape: predictions/target are [1024, 8192] fp32.
#define BB 1024
#define NN 8192
#define KK 10
#define THREADS 128
#define NWARP (THREADS / 32)         // 4
#define ITERS ((NN / 4) / THREADS)   // 16 float4 iters per thread (select)
#define GITERS ((NN / 4) / 64)       // 32 float4 iters per 64-thread group (hinge)
#define CAP 128                      // candidate buffer (4 per lane of warp 0)
#define FILT_T 0.995f

typedef unsigned long long u64;

// Static device scratch (no allocations allowed).
__device__ float g_sel[BB][32];      // [0:10) c_k, [10:20) t_k, [20:30) p_k
__device__ float g_partial[BB];
__device__ unsigned int g_ticket;    // zero-init at load; reset by last block

__device__ __forceinline__ u64 umax64(u64 a, u64 b) { return a > b ? a : b; }

// key = ((fbits+1)<<13) | (NN-1-idx): monotone in value (targets >= 0),
// min-index tie-break, all keys > 0 and globally unique per row.
__device__ __forceinline__ u64 pack_key(float v, int idx) {
    return (((u64)__float_as_uint(v) + 1ull) << 13) | (u64)(NN - 1 - idx);
}

__device__ __forceinline__ u64 pack2(float lo, float hi) {
    u64 r; asm("mov.b64 %0, {%1, %2};" : "=l"(r) : "f"(lo), "f"(hi)); return r;
}
__device__ __forceinline__ u64 add2(u64 a, u64 b) {
    u64 r; asm("add.rn.f32x2 %0, %1, %2;" : "=l"(r) : "l"(a), "l"(b)); return r;
}
__device__ __forceinline__ float sum2(u64 a) {
    float x, y; asm("mov.b64 {%0, %1}, %2;" : "=f"(x), "=f"(y) : "l"(a));
    return x + y;
}

// ============================================================================
// Kernel 1: per-row top-10 selection (streams target, gathers 10 preds).
// ============================================================================
__global__ __launch_bounds__(THREADS, 8)
void vml_select(const float* __restrict__ pred,
                const float* __restrict__ targ) {
    const int row  = blockIdx.x;
    const int tid  = threadIdx.x;
    const int lane = tid & 31;
    const int warp = tid >> 5;

    const float4* t4 = reinterpret_cast<const float4*>(targ + (size_t)row * NN);
    const float* pred_row = pred + (size_t)row * NN;

    __shared__ int  s_count;
    __shared__ u64  s_cand[CAP];
    __shared__ u64  s_warp_top[NWARP * KK];   // fallback only (40 keys)
    __shared__ float s_t[KK];
    __shared__ int   s_i[KK];

    if (tid == 0) s_count = 0;
    __syncthreads();

    // Sweep 1: pure streaming load + per-float4 max (independent chains).
    float vm[ITERS];
#pragma unroll
    for (int it = 0; it < ITERS; it++) {
        float4 t = t4[tid + it * THREADS];
        vm[it] = fmaxf(fmaxf(t.x, t.y), fmaxf(t.z, t.w));
    }

    // Sweep 2: rare candidate extraction (~2% of float4s); reload hits L1/L2.
#pragma unroll
    for (int it = 0; it < ITERS; it++) {
        if (vm[it] > FILT_T) {
            const int f4i = tid + it * THREADS;
            float4 t = t4[f4i];
            const int base = f4i * 4;
            float vals[4] = {t.x, t.y, t.z, t.w};
#pragma unroll
            for (int e = 0; e < 4; e++) {
                if (vals[e] > FILT_T) {
                    int p = atomicAdd(&s_count, 1);
                    if (p < CAP) s_cand[p] = pack_key(vals[e], base + e);
                }
            }
        }
    }
    __syncthreads();

    const bool filter_ok = (s_count >= KK && s_count <= CAP);

    if (filter_ok) {
        if (warp == 0) {
            const int cnt = s_count;
            u64 loc[CAP / 32];
#pragma unroll
            for (int i = 0; i < CAP / 32; i++) {
                int ix = lane + i * 32;
                loc[i] = (ix < cnt) ? s_cand[ix] : 0ull;
            }
#pragma unroll
            for (int r = 0; r < KK; r++) {
                u64 lm = loc[0];
#pragma unroll
                for (int i = 1; i < CAP / 32; i++) lm = umax64(lm, loc[i]);
                u64 m = lm;
#pragma unroll
                for (int off = 16; off > 0; off >>= 1)
                    m = umax64(m, __shfl_xor_sync(0xffffffffu, m, off));
#pragma unroll
                for (int i = 0; i < CAP / 32; i++)
                    if (loc[i] == m) loc[i] = 0ull;   // unique keys: one match
                if (lane == r) {
                    s_t[r] = __uint_as_float((unsigned)(m >> 13) - 1u);
                    s_i[r] = (NN - 1) - (int)(m & (u64)(NN - 1));
                }
            }
        }
    } else {
        // Exact fallback (verified round-2 path).
        u64 v[KK];
#pragma unroll
        for (int i = 0; i < KK; i++) v[i] = 0ull;
#pragma unroll
        for (int it = 0; it < ITERS; it++) {
            const int f4i = tid + it * THREADS;
            float4 t = t4[f4i];
            const int base = f4i * 4;
            float vals[4] = {t.x, t.y, t.z, t.w};
#pragma unroll
            for (int e = 0; e < 4; e++) {
                u64 key = pack_key(vals[e], base + e);
                if (key > v[KK - 1]) {
                    v[KK - 1] = key;
#pragma unroll
                    for (int i = KK - 1; i > 0; i--) {
                        if (v[i] > v[i - 1]) { u64 tmp = v[i - 1]; v[i - 1] = v[i]; v[i] = tmp; }
                    }
                }
            }
        }
        {
            u64 head = v[0];
#pragma unroll
            for (int r = 0; r < KK; r++) {
                u64 m = head;
#pragma unroll
                for (int off = 16; off > 0; off >>= 1)
                    m = umax64(m, __shfl_xor_sync(0xffffffffu, m, off));
                if (head == m) {
#pragma unroll
                    for (int i = 0; i < KK - 1; i++) v[i] = v[i + 1];
                    v[KK - 1] = 0ull;
                    head = v[0];
                }
                if (lane == 0) s_warp_top[warp * KK + r] = m;
            }
        }
        __syncthreads();
        if (warp == 0) {
            u64 k0 = s_warp_top[lane];
            u64 k1 = (lane + 32 < NWARP * KK) ? s_warp_top[lane + 32] : 0ull;
#pragma unroll
            for (int r = 0; r < KK; r++) {
                u64 m = umax64(k0, k1);
#pragma unroll
                for (int off = 16; off > 0; off >>= 1)
                    m = umax64(m, __shfl_xor_sync(0xffffffffu, m, off));
                if (k0 == m) k0 = 0ull;
                else if (k1 == m) k1 = 0ull;
                if (lane == r) {
                    s_t[r] = __uint_as_float((unsigned)(m >> 13) - 1u);
                    s_i[r] = (NN - 1) - (int)(m & (u64)(NN - 1));
                }
            }
        }
    }
    __syncthreads();

    // Gather top preds; write c_k, t_k, p_k to staging.
    if (tid < KK) {
        float tk = s_t[tid];
        float pk = pred_row[s_i[tid]];
        g_sel[row][tid]      = 0.5f * tk - pk;   // c_k
        g_sel[row][10 + tid] = tk;
        g_sel[row][20 + tid] = pk;
    }
}

// ============================================================================
// Kernel 2: hinge sums. K split across warp halves: warps 0-1 handle k=0..4,
// warps 2-3 handle k=5..9; each 64-thread group streams the FULL row. Halved
// accumulator registers -> deeper load pipelining. DRAM traffic unchanged
// (second group's loads hit L1).
// ============================================================================
__global__ __launch_bounds__(THREADS, 8)
void vml_hinge(const float* __restrict__ pred,
               float* __restrict__ out) {
    const int row  = blockIdx.x;
    const int tid  = threadIdx.x;
    const int lane = tid & 31;
    const int warp = tid >> 5;
    const int gtid = tid & 63;          // index within 64-thread group
    const int grp  = tid >> 6;          // 0: k 0-4, 1: k 5-9
    const int kbase = grp * 5;

    const float4* p4 = reinterpret_cast<const float4*>(pred + (size_t)row * NN);

    __shared__ float s_ctp[32];         // c 0..9, t 10..19, p 20..29
    __shared__ float s_sums[NWARP][5];  // per-warp partials for its 5 k's
    __shared__ float s_sumx[2];         // warps 0,1 (group 0 covers full row)
    __shared__ float s_loss[KK];
    __shared__ bool  s_last;

    if (tid < 30) s_ctp[tid] = g_sel[row][tid];
    __syncthreads();

    // A_k = sum_j |c_k + x_j|; relu(d) = 0.5*(d+|d|) exactly in fp32.
    const u64 ABSMASK = 0x7fffffff7fffffffull;
    u64 c2[5], a2[5];
#pragma unroll
    for (int k = 0; k < 5; k++) {
        float c = s_ctp[kbase + k];
        c2[k] = pack2(c, c);
        a2[k] = 0ull;
    }
    u64 sx2 = 0ull;

#pragma unroll
    for (int it = 0; it < GITERS; it++) {
        float4 p = p4[gtid + it * 64];
        u64 x01 = pack2(p.x, p.y);
        u64 x23 = pack2(p.z, p.w);
        sx2 = add2(sx2, x01);
        sx2 = add2(sx2, x23);
#pragma unroll
        for (int k = 0; k < 5; k++) {
            u64 d0 = add2(c2[k], x01) & ABSMASK;
            a2[k] = add2(a2[k], d0);
            u64 d1 = add2(c2[k], x23) & ABSMASK;
            a2[k] = add2(a2[k], d1);
        }
    }

    float A[5];
#pragma unroll
    for (int k = 0; k < 5; k++) A[k] = sum2(a2[k]);
    float sx = sum2(sx2);

#pragma unroll
    for (int k = 0; k < 5; k++) {
#pragma unroll
        for (int off = 16; off > 0; off >>= 1)
            A[k] += __shfl_xor_sync(0xffffffffu, A[k], off);
    }
#pragma unroll
    for (int off = 16; off > 0; off >>= 1)
        sx += __shfl_xor_sync(0xffffffffu, sx, off);

    if (lane == 0) {
#pragma unroll
        for (int k = 0; k < 5; k++) s_sums[warp][k] = A[k];
        if (warp < 2) s_sumx[warp] = sx;   // group 0 covers the row once
    }
    __syncthreads();

    if (tid < KK) {
        const int k = tid;
        const int g = k / 5;                 // which warp pair owns this k
        const int kk = k - g * 5;
        float Ak = s_sums[g * 2][kk] + s_sums[g * 2 + 1][kk];
        float Sx = s_sumx[0] + s_sumx[1];
        float ck = s_ctp[k];
        float S_full = 0.5f * (fmaf((float)NN, ck, Sx) + Ak);
        float sub = 0.f;
        for (int r = 0; r <= k; r++) sub += fmaxf(ck + s_ctp[20 + r], 0.f);
        float per = (S_full - sub) / (float)(NN - k);
        s_loss[k] = (s_ctp[10 + k] > 0.25f) ? per : 0.f;
    }
    __syncthreads();

    if (tid == 0) {
        float acc = 0.f;
#pragma unroll
        for (int k = 0; k < KK; k++) acc += s_loss[k];
        g_partial[row] = acc;
        __threadfence();
        unsigned t = atomicAdd(&g_ticket, 1u);
        s_last = (t == BB - 1);
    }
    __syncthreads();

    // Last block: deterministic reduction of all 1024 row partials.
    if (s_last) {
        __threadfence();
        float v = 0.f;
#pragma unroll
        for (int j = 0; j < BB / THREADS; j++)
            v += g_partial[tid + j * THREADS];
        __shared__ float sred[THREADS];
        sred[tid] = v;
        __syncthreads();
#pragma unroll
        for (int stride = THREADS / 2; stride > 0; stride >>= 1) {
            if (tid < stride) sred[tid] += sred[tid + stride];
            __syncthreads();
        }
        if (tid == 0) {
            out[0] = sred[0];
            g_ticket = 0;   // reset for next graph replay
        }
    }
}

extern "C" void kernel_launch(void* const* d_in, const int* in_sizes, int n_in,
                              void* d_out, int out_size) {
    const float* pred = (const float*)d_in[0];
    const float* targ = (const float*)d_in[1];
    vml_select<<<BB, THREADS>>>(pred, targ);
    vml_hinge<<<BB, THREADS>>>(pred, (float*)d_out);
}

// round 12
// speedup vs baseline: 1.0052x; 1.0052x over previous
#include <cuda_runtime.h>
#include <cstdint>

// Fixed problem shape: predictions/target are [1024, 8192] fp32.
#define BB 1024
#define NN 8192
#define KK 10
#define THREADS 128
#define NWARP (THREADS / 32)         // 4
#define ITERS ((NN / 4) / THREADS)   // 16 float4 iters per thread
#define CAP 128                      // candidate buffer (4 per lane of warp 0)
#define FILT_T 0.995f

typedef unsigned long long u64;

// Static device scratch (no allocations allowed).
__device__ float g_sel[BB][32];      // [0:10) c_k, [10:20) t_k, [20:30) p_k
__device__ float g_partial[BB];
__device__ unsigned int g_ticket;    // zero-init at load; reset by last block

__device__ __forceinline__ u64 umax64(u64 a, u64 b) { return a > b ? a : b; }

// key = ((fbits+1)<<13) | (NN-1-idx): monotone in value (targets >= 0),
// min-index tie-break, all keys > 0 and globally unique per row.
__device__ __forceinline__ u64 pack_key(float v, int idx) {
    return (((u64)__float_as_uint(v) + 1ull) << 13) | (u64)(NN - 1 - idx);
}

__device__ __forceinline__ u64 pack2(float lo, float hi) {
    u64 r; asm("mov.b64 %0, {%1, %2};" : "=l"(r) : "f"(lo), "f"(hi)); return r;
}
__device__ __forceinline__ u64 add2(u64 a, u64 b) {
    u64 r; asm("add.rn.f32x2 %0, %1, %2;" : "=l"(r) : "l"(a), "l"(b)); return r;
}
__device__ __forceinline__ void unpack2(u64 a, float& lo, float& hi) {
    asm("mov.b64 {%0, %1}, %2;" : "=f"(lo), "=f"(hi) : "l"(a));
}
__device__ __forceinline__ float sum2(u64 a) {
    float x, y; unpack2(a, x, y); return x + y;
}

// ============================================================================
// Kernel 1: per-row top-10 selection (streams target, gathers 10 preds).
// ============================================================================
__global__ __launch_bounds__(THREADS, 8)
void vml_select(const float* __restrict__ pred,
                const float* __restrict__ targ) {
    const int row  = blockIdx.x;
    const int tid  = threadIdx.x;
    const int lane = tid & 31;
    const int warp = tid >> 5;

    const float4* t4 = reinterpret_cast<const float4*>(targ + (size_t)row * NN);
    const float* pred_row = pred + (size_t)row * NN;

    __shared__ int  s_count;
    __shared__ u64  s_cand[CAP];
    __shared__ u64  s_warp_top[NWARP * KK];   // fallback only (40 keys)
    __shared__ float s_t[KK];
    __shared__ int   s_i[KK];

    if (tid == 0) s_count = 0;
    __syncthreads();

    // Sweep 1: pure streaming load + per-float4 max (independent chains).
    float vm[ITERS];
#pragma unroll
    for (int it = 0; it < ITERS; it++) {
        float4 t = t4[tid + it * THREADS];
        vm[it] = fmaxf(fmaxf(t.x, t.y), fmaxf(t.z, t.w));
    }

    // Sweep 2: rare candidate extraction (~2% of float4s); reload hits L1/L2.
#pragma unroll
    for (int it = 0; it < ITERS; it++) {
        if (vm[it] > FILT_T) {
            const int f4i = tid + it * THREADS;
            float4 t = t4[f4i];
            const int base = f4i * 4;
            float vals[4] = {t.x, t.y, t.z, t.w};
#pragma unroll
            for (int e = 0; e < 4; e++) {
                if (vals[e] > FILT_T) {
                    int p = atomicAdd(&s_count, 1);
                    if (p < CAP) s_cand[p] = pack_key(vals[e], base + e);
                }
            }
        }
    }
    __syncthreads();

    const bool filter_ok = (s_count >= KK && s_count <= CAP);

    if (filter_ok) {
        if (warp == 0) {
            const int cnt = s_count;
            u64 loc[CAP / 32];
#pragma unroll
            for (int i = 0; i < CAP / 32; i++) {
                int ix = lane + i * 32;
                loc[i] = (ix < cnt) ? s_cand[ix] : 0ull;
            }
#pragma unroll
            for (int r = 0; r < KK; r++) {
                u64 lm = loc[0];
#pragma unroll
                for (int i = 1; i < CAP / 32; i++) lm = umax64(lm, loc[i]);
                u64 m = lm;
#pragma unroll
                for (int off = 16; off > 0; off >>= 1)
                    m = umax64(m, __shfl_xor_sync(0xffffffffu, m, off));
#pragma unroll
                for (int i = 0; i < CAP / 32; i++)
                    if (loc[i] == m) loc[i] = 0ull;   // unique keys: one match
                if (lane == r) {
                    s_t[r] = __uint_as_float((unsigned)(m >> 13) - 1u);
                    s_i[r] = (NN - 1) - (int)(m & (u64)(NN - 1));
                }
            }
        }
    } else {
        // Exact fallback (verified round-2 path).
        u64 v[KK];
#pragma unroll
        for (int i = 0; i < KK; i++) v[i] = 0ull;
#pragma unroll
        for (int it = 0; it < ITERS; it++) {
            const int f4i = tid + it * THREADS;
            float4 t = t4[f4i];
            const int base = f4i * 4;
            float vals[4] = {t.x, t.y, t.z, t.w};
#pragma unroll
            for (int e = 0; e < 4; e++) {
                u64 key = pack_key(vals[e], base + e);
                if (key > v[KK - 1]) {
                    v[KK - 1] = key;
#pragma unroll
                    for (int i = KK - 1; i > 0; i--) {
                        if (v[i] > v[i - 1]) { u64 tmp = v[i - 1]; v[i - 1] = v[i]; v[i] = tmp; }
                    }
                }
            }
        }
        {
            u64 head = v[0];
#pragma unroll
            for (int r = 0; r < KK; r++) {
                u64 m = head;
#pragma unroll
                for (int off = 16; off > 0; off >>= 1)
                    m = umax64(m, __shfl_xor_sync(0xffffffffu, m, off));
                if (head == m) {
#pragma unroll
                    for (int i = 0; i < KK - 1; i++) v[i] = v[i + 1];
                    v[KK - 1] = 0ull;
                    head = v[0];
                }
                if (lane == 0) s_warp_top[warp * KK + r] = m;
            }
        }
        __syncthreads();
        if (warp == 0) {
            u64 k0 = s_warp_top[lane];
            u64 k1 = (lane + 32 < NWARP * KK) ? s_warp_top[lane + 32] : 0ull;
#pragma unroll
            for (int r = 0; r < KK; r++) {
                u64 m = umax64(k0, k1);
#pragma unroll
                for (int off = 16; off > 0; off >>= 1)
                    m = umax64(m, __shfl_xor_sync(0xffffffffu, m, off));
                if (k0 == m) k0 = 0ull;
                else if (k1 == m) k1 = 0ull;
                if (lane == r) {
                    s_t[r] = __uint_as_float((unsigned)(m >> 13) - 1u);
                    s_i[r] = (NN - 1) - (int)(m & (u64)(NN - 1));
                }
            }
        }
    }
    __syncthreads();

    // Gather top preds; write c_k, t_k, p_k to staging.
    if (tid < KK) {
        float tk = s_t[tid];
        float pk = pred_row[s_i[tid]];
        g_sel[row][tid]      = 0.5f * tk - pk;   // c_k
        g_sel[row][10 + tid] = tk;
        g_sel[row][20 + tid] = pk;
    }
}

// ============================================================================
// Kernel 2: hinge sums. Inner loop: packed add2 + scalar FADD with free |abs|
// input modifier (no LOP3 mask ops). No smem staging / barrier before the
// loop: c_k comes via broadcast __ldg, so pred loads issue immediately.
// ============================================================================
__global__ __launch_bounds__(THREADS, 8)
void vml_hinge(const float* __restrict__ pred,
               float* __restrict__ out) {
    const int row  = blockIdx.x;
    const int tid  = threadIdx.x;
    const int lane = tid & 31;
    const int warp = tid >> 5;

    const float4* p4 = reinterpret_cast<const float4*>(pred + (size_t)row * NN);
    const float* selr = g_sel[row];

    __shared__ float s_sums[NWARP][KK];
    __shared__ float s_sumx[NWARP];
    __shared__ float s_loss[KK];
    __shared__ bool  s_last;

    // Broadcast c_k (L2/L1 hit after first warp; no barrier needed).
    u64 c2[KK];
    float aL[KK], aH[KK];
#pragma unroll
    for (int k = 0; k < KK; k++) {
        float c = __ldg(selr + k);
        c2[k] = pack2(c, c);
        aL[k] = 0.f; aH[k] = 0.f;
    }
    u64 sx2 = 0ull;

    // A_k = sum_j |c_k + x_j|; relu(d) = 0.5*(d+|d|) exactly in fp32, so
    // sum_j relu(c_k+x_j) = 0.5*(NN*c_k + Sx + A_k).
#pragma unroll
    for (int it = 0; it < ITERS; it++) {
        float4 p = p4[tid + it * THREADS];
        u64 x01 = pack2(p.x, p.y);
        u64 x23 = pack2(p.z, p.w);
        sx2 = add2(sx2, x01);
        sx2 = add2(sx2, x23);
#pragma unroll
        for (int k = 0; k < KK; k++) {
            u64 d01 = add2(c2[k], x01);
            float dlo, dhi; unpack2(d01, dlo, dhi);
            aL[k] += fabsf(dlo);              // FADD with |.| modifier
            aH[k] += fabsf(dhi);
            u64 d23 = add2(c2[k], x23);
            unpack2(d23, dlo, dhi);
            aL[k] += fabsf(dlo);
            aH[k] += fabsf(dhi);
        }
    }

    float A[KK];
#pragma unroll
    for (int k = 0; k < KK; k++) A[k] = aL[k] + aH[k];
    float sx = sum2(sx2);

#pragma unroll
    for (int k = 0; k < KK; k++) {
#pragma unroll
        for (int off = 16; off > 0; off >>= 1)
            A[k] += __shfl_xor_sync(0xffffffffu, A[k], off);
    }
#pragma unroll
    for (int off = 16; off > 0; off >>= 1)
        sx += __shfl_xor_sync(0xffffffffu, sx, off);

    if (lane == 0) {
#pragma unroll
        for (int k = 0; k < KK; k++) s_sums[warp][k] = A[k];
        s_sumx[warp] = sx;
    }
    __syncthreads();

    if (tid < KK) {
        const int k = tid;
        float Ak = 0.f, Sx = 0.f;
#pragma unroll
        for (int w = 0; w < NWARP; w++) { Ak += s_sums[w][k]; Sx += s_sumx[w]; }
        float ck = selr[k];
        float S_full = 0.5f * (fmaf((float)NN, ck, Sx) + Ak);
        float sub = 0.f;
        for (int r = 0; r <= k; r++) sub += fmaxf(ck + selr[20 + r], 0.f);
        float per = (S_full - sub) / (float)(NN - k);
        s_loss[k] = (selr[10 + k] > 0.25f) ? per : 0.f;
    }
    __syncthreads();

    if (tid == 0) {
        float acc = 0.f;
#pragma unroll
        for (int k = 0; k < KK; k++) acc += s_loss[k];
        g_partial[row] = acc;
        __threadfence();
        unsigned t = atomicAdd(&g_ticket, 1u);
        s_last = (t == BB - 1);
    }
    __syncthreads();

    // Last block: deterministic reduction of all 1024 row partials.
    if (s_last) {
        __threadfence();
        float v = 0.f;
#pragma unroll
        for (int j = 0; j < BB / THREADS; j++)
            v += g_partial[tid + j * THREADS];
        __shared__ float sred[THREADS];
        sred[tid] = v;
        __syncthreads();
#pragma unroll
        for (int stride = THREADS / 2; stride > 0; stride >>= 1) {
            if (tid < stride) sred[tid] += sred[tid + stride];
            __syncthreads();
        }
        if (tid == 0) {
            out[0] = sred[0];
            g_ticket = 0;   // reset for next graph replay
        }
    }
}

extern "C" void kernel_launch(void* const* d_in, const int* in_sizes, int n_in,
                              void* d_out, int out_size) {
    const float* pred = (const float*)d_in[0];
    const float* targ = (const float*)d_in[1];
    vml_select<<<BB, THREADS>>>(pred, targ);
    vml_hinge<<<BB, THREADS>>>(pred, (float*)d_out);
}